// round 4
// baseline (speedup 1.0000x reference)
#include <cuda_runtime.h>

#define NJ   32
#define TPB  128
#define EPB  (TPB * 2)
#define OUTC 94

typedef unsigned long long u64;

// ---- smem byte layout ----
#define BY_U    (TPB * OUTC * 4)     // 48128: u64 dup-const region starts here (8-aligned)
#define U_JOFF  0                    // 32*7 u64
#define U_P     224                  // 32*4 u64
#define U_TGT   352                  // 4*10 u64
#define U_DB    392                  // 10 u64
#define N_U     402
#define BY_REST (BY_U + N_U * 8)     // 51344
#define BY_JLO  (BY_REST + 128)
#define BY_JUP  (BY_JLO + 128)
#define SMEM_BYTES (BY_JUP + 128)    // 51728

// ---- packed f32x2 primitives (sm_103a FFMA2 path) ----
__device__ __forceinline__ u64 f2pack(float lo, float hi) {
    u64 r;
    asm("mov.b64 %0, {%1, %2};" : "=l"(r)
        : "r"(__float_as_uint(lo)), "r"(__float_as_uint(hi)));
    return r;
}
__device__ __forceinline__ void f2unp(u64 a, float& lo, float& hi) {
    unsigned l, h;
    asm("mov.b64 {%0, %1}, %2;" : "=r"(l), "=r"(h) : "l"(a));
    lo = __uint_as_float(l); hi = __uint_as_float(h);
}
__device__ __forceinline__ u64 f2mul(u64 a, u64 b) {
    u64 r; asm("mul.rn.f32x2 %0, %1, %2;" : "=l"(r) : "l"(a), "l"(b)); return r;
}
__device__ __forceinline__ u64 f2add(u64 a, u64 b) {
    u64 r; asm("add.rn.f32x2 %0, %1, %2;" : "=l"(r) : "l"(a), "l"(b)); return r;
}
__device__ __forceinline__ u64 f2fma(u64 a, u64 b, u64 c) {
    u64 r; asm("fma.rn.f32x2 %0, %1, %2, %3;" : "=l"(r) : "l"(a), "l"(b), "l"(c)); return r;
}

#define C_NEG1  0xBF800000BF800000ULL
#define C_TWO   0x4000000040000000ULL
#define C_NHALF 0xBF000000BF000000ULL

struct V2 { u64 x, y, z; };
struct Q2 { u64 x, y, z, w; };

// scalar per-element tail of se3_log: scale and 'a' coefficient
__device__ __forceinline__ void log_scalars(float nv2, float qw,
                                            float& scale, float& a) {
    float nv  = sqrtf(fmaxf(nv2, 1e-14f));
    float qwc = fabsf(qw);                       // canonicalized w (>= 0)
    // atan2(nv, qwc), both args >= 0
    float mn = fminf(nv, qwc), mx = fmaxf(nv, qwc);
    float r  = __fdividef(mn, mx);
    float r2 = r * r;
    float p = fmaf(r2, -0.0117212f,  0.05265332f);
    p = fmaf(r2, p, -0.11643287f);
    p = fmaf(r2, p,  0.19354346f);
    p = fmaf(r2, p, -0.33262347f);
    p = fmaf(r2, p,  0.99997726f);
    float th0 = r * p;
    float at  = (nv > qwc) ? (1.57079632679489662f - th0) : th0;
    float angle = 2.0f * at;
    float wsafe = (qwc > 1e-8f) ? qwc : 1.0f;
    scale = (nv < 1e-6f) ? __fdividef(2.0f, wsafe) : __fdividef(angle, nv);
    float th2  = angle * angle;
    float abig = __fdividef(1.0f - 0.5f * scale * qwc, th2);
    a = (angle < 1e-4f) ? (1.0f / 12.0f + th2 * (1.0f / 720.0f)) : abig;
}

// packed se3_log for unit quaternion pair
__device__ __forceinline__ void se3_log2(V2 t, Q2 q, V2& rho, V2& phi) {
    const u64 NEG1 = C_NEG1, NHALF = C_NHALF;
    float qwA, qwB; f2unp(q.w, qwA, qwB);
    u64 sg = f2pack(qwA < 0.0f ? -1.0f : 1.0f, qwB < 0.0f ? -1.0f : 1.0f);
    u64 qx = f2mul(q.x, sg), qy = f2mul(q.y, sg), qz = f2mul(q.z, sg);
    u64 nv2 = f2fma(qx, qx, f2fma(qy, qy, f2mul(qz, qz)));
    float n2A, n2B; f2unp(nv2, n2A, n2B);
    float scA, aA, scB, aB;
    log_scalars(n2A, qwA, scA, aA);
    log_scalars(n2B, qwB, scB, aB);
    u64 sc = f2pack(scA, scB), a2 = f2pack(aA, aB);
    phi.x = f2mul(qx, sc); phi.y = f2mul(qy, sc); phi.z = f2mul(qz, sc);
    u64 nx = f2mul(phi.x, NEG1), ny = f2mul(phi.y, NEG1), nz = f2mul(phi.z, NEG1);
    // pt = phi x t
    u64 ptx = f2fma(phi.y, t.z, f2mul(nz, t.y));
    u64 pty = f2fma(phi.z, t.x, f2mul(nx, t.z));
    u64 ptz = f2fma(phi.x, t.y, f2mul(ny, t.x));
    // ppt = phi x pt
    u64 px = f2fma(phi.y, ptz, f2mul(nz, pty));
    u64 py = f2fma(phi.z, ptx, f2mul(nx, ptz));
    u64 pz = f2fma(phi.x, pty, f2mul(ny, ptx));
    rho.x = f2fma(a2, px, f2fma(NHALF, ptx, t.x));
    rho.y = f2fma(a2, py, f2fma(NHALF, pty, t.y));
    rho.z = f2fma(a2, pz, f2fma(NHALF, ptz, t.z));
}

// log( inv(target) o actual ); tp = 10 dup-u64: [-t(3), qi(4), -qi.xyz(3)]
__device__ __forceinline__ void pose_err2(const u64* tp, V2 at, Q2 aq,
                                          V2& rho, V2& phi) {
    const u64 TWO = C_TWO;
    V2 d{f2add(at.x, tp[0]), f2add(at.y, tp[1]), f2add(at.z, tp[2])};
    u64 qix = tp[3], qiy = tp[4], qiz = tp[5], qiw = tp[6];
    u64 nx = tp[7], ny = tp[8], nz = tp[9];
    // pe = qrot(qi, d)
    u64 ux = f2fma(qiy, d.z, f2mul(nz, d.y)); ux = f2fma(qiw, d.x, ux);
    u64 uy = f2fma(qiz, d.x, f2mul(nx, d.z)); uy = f2fma(qiw, d.y, uy);
    u64 uz = f2fma(qix, d.y, f2mul(ny, d.x)); uz = f2fma(qiw, d.z, uz);
    u64 cx = f2fma(qiy, uz, f2mul(nz, uy));
    u64 cy = f2fma(qiz, ux, f2mul(nx, uz));
    u64 cz = f2fma(qix, uy, f2mul(ny, ux));
    V2 pe{f2fma(TWO, cx, d.x), f2fma(TWO, cy, d.y), f2fma(TWO, cz, d.z)};
    // qe = qmul(qi, aq)
    Q2 qe;
    qe.w = f2fma(nx, aq.x, f2fma(ny, aq.y, f2fma(nz, aq.z, f2mul(qiw, aq.w))));
    qe.x = f2fma(qiy, aq.z, f2fma(nz, aq.y, f2fma(qiw, aq.x, f2mul(qix, aq.w))));
    qe.y = f2fma(qiz, aq.x, f2fma(nx, aq.z, f2fma(qiw, aq.y, f2mul(qiy, aq.w))));
    qe.z = f2fma(qix, aq.y, f2fma(ny, aq.x, f2fma(qiw, aq.z, f2mul(qiz, aq.w))));
    se3_log2(pe, qe, rho, phi);
}

__global__ void __launch_bounds__(TPB)
ik_residual_kernel(const float* __restrict__ cfg,
                   const float* __restrict__ base,
                   const float* __restrict__ tgt,
                   const float* __restrict__ dbase,
                   const float* __restrict__ rest,
                   const float* __restrict__ joff,
                   const float* __restrict__ jaxis,
                   const float* __restrict__ jlo,
                   const float* __restrict__ jup,
                   float* __restrict__ out) {
    extern __shared__ __align__(16) unsigned char sm[];
    float* s   = (float*)sm;                 // output staging (TPB*94 floats)
    u64*   U   = (u64*)(sm + BY_U);          // dup-packed constants
    float* RST = (float*)(sm + BY_REST);
    float* LO  = (float*)(sm + BY_JLO);
    float* UP  = (float*)(sm + BY_JUP);

    const u64 NEG1 = C_NEG1, TWO = C_TWO;
    const int t  = threadIdx.x;
    const int e0 = blockIdx.x * EPB;

    // ---- stage base poses (scratch in s) + dup-packed constants ----
    {
        const float* gb = base + (size_t)e0 * 7;
        for (int i = t; i < EPB * 7; i += TPB) s[i] = gb[i];
        for (int i = t; i < 224; i += TPB) {
            float v = __ldg(joff + i);
            ((float2*)(U + U_JOFF + i))[0] = make_float2(v, v);
        }
        if (t < 32) {
            RST[t] = __ldg(rest + t);
            LO[t]  = __ldg(jlo + t);
            UP[t]  = __ldg(jup + t);
            // P_j = oq_j (x) [axis_j, 0]
            float ox = __ldg(joff + t * 7 + 3), oy = __ldg(joff + t * 7 + 4);
            float oz = __ldg(joff + t * 7 + 5), ow = __ldg(joff + t * 7 + 6);
            float ax = __ldg(jaxis + t * 3 + 0), ay = __ldg(jaxis + t * 3 + 1);
            float az = __ldg(jaxis + t * 3 + 2);
            float p0 = ow * ax + oy * az - oz * ay;
            float p1 = ow * ay + oz * ax - ox * az;
            float p2 = ow * az + ox * ay - oy * ax;
            float p3 = -(ox * ax + oy * ay + oz * az);
            float2* pd = (float2*)(U + U_P + t * 4);
            pd[0] = make_float2(p0, p0); pd[1] = make_float2(p1, p1);
            pd[2] = make_float2(p2, p2); pd[3] = make_float2(p3, p3);
        }
        if (t < 5) {
            const float* src = (t < 4) ? (tgt + t * 7) : dbase;
            float2* dst = (float2*)(U + ((t < 4) ? (U_TGT + t * 10) : U_DB));
            float tx = __ldg(src + 0), ty = __ldg(src + 1), tz = __ldg(src + 2);
            float qx = __ldg(src + 3), qy = __ldg(src + 4);
            float qz = __ldg(src + 5), qw = __ldg(src + 6);
            dst[0] = make_float2(-tx, -tx); dst[1] = make_float2(-ty, -ty);
            dst[2] = make_float2(-tz, -tz);
            dst[3] = make_float2(-qx, -qx); dst[4] = make_float2(-qy, -qy);
            dst[5] = make_float2(-qz, -qz); dst[6] = make_float2(qw, qw);
            dst[7] = make_float2(qx, qx);   dst[8] = make_float2(qy, qy);
            dst[9] = make_float2(qz, qz);
        }
    }
    __syncthreads();

    // pack both elements' base poses into f32x2 state
    V2 Tt; Q2 Tq;
    {
        const float* a = s + t * 7;
        const float* b = s + (TPB + t) * 7;
        Tt.x = f2pack(a[0], b[0]); Tt.y = f2pack(a[1], b[1]); Tt.z = f2pack(a[2], b[2]);
        Tq.x = f2pack(a[3], b[3]); Tq.y = f2pack(a[4], b[4]);
        Tq.z = f2pack(a[5], b[5]); Tq.w = f2pack(a[6], b[6]);
    }
    V2 bt = Tt; Q2 bq = Tq;
    __syncthreads();   // scratch becomes output staging

    // ---- load both cfg rows ----
    float thA[NJ], thB[NJ];
    {
        const float4* cA = (const float4*)(cfg + (size_t)(e0 + t) * NJ);
        const float4* cB = (const float4*)(cfg + (size_t)(e0 + TPB + t) * NJ);
        #pragma unroll
        for (int i = 0; i < NJ / 4; i++) {
            float4 a = __ldg(cA + i);
            thA[4*i+0] = a.x; thA[4*i+1] = a.y; thA[4*i+2] = a.z; thA[4*i+3] = a.w;
            float4 b = __ldg(cB + i);
            thB[4*i+0] = b.x; thB[4*i+1] = b.y; thB[4*i+2] = b.z; thB[4*i+3] = b.w;
        }
    }

    float* row = s + t * OUTC;
    float bres[30];

    // ---- packed dual FK chain ----
    #pragma unroll
    for (int j = 0; j < NJ; j++) {
        // A limit/rest -> smem row (B done in phase 2)
        float limA = fmaxf(thA[j] - UP[j], 0.0f) + fminf(thA[j] - LO[j], 0.0f);
        row[24 + j] = limA * 10.0f;
        row[56 + j] = (thA[j] - RST[j]) * 0.1f;

        const u64* o  = U + U_JOFF + j * 7;
        u64 otx = o[0], oty = o[1], otz = o[2];
        u64 nqx = f2mul(Tq.x, NEG1), nqy = f2mul(Tq.y, NEG1), nqz = f2mul(Tq.z, NEG1);
        // rt = qrot(Tq, ot); Tt += ot + 2*c
        u64 ux = f2fma(Tq.y, otz, f2mul(nqz, oty)); ux = f2fma(Tq.w, otx, ux);
        u64 uy = f2fma(Tq.z, otx, f2mul(nqx, otz)); uy = f2fma(Tq.w, oty, uy);
        u64 uz = f2fma(Tq.x, oty, f2mul(nqy, otx)); uz = f2fma(Tq.w, otz, uz);
        u64 cx = f2fma(Tq.y, uz, f2mul(nqz, uy));
        u64 cy = f2fma(Tq.z, ux, f2mul(nqx, uz));
        u64 cz = f2fma(Tq.x, uy, f2mul(nqy, ux));
        Tt.x = f2fma(TWO, cx, f2add(Tt.x, otx));
        Tt.y = f2fma(TWO, cy, f2add(Tt.y, oty));
        Tt.z = f2fma(TWO, cz, f2add(Tt.z, otz));
        // M = ch*oq + sh*P
        float shA, chA, shB, chB;
        __sincosf(0.5f * thA[j], &shA, &chA);
        __sincosf(0.5f * thB[j], &shB, &chB);
        u64 sh = f2pack(shA, shB), ch = f2pack(chA, chB);
        const u64* pj = U + U_P + j * 4;
        u64 Mx = f2fma(sh, pj[0], f2mul(ch, o[3]));
        u64 My = f2fma(sh, pj[1], f2mul(ch, o[4]));
        u64 Mz = f2fma(sh, pj[2], f2mul(ch, o[5]));
        u64 Mw = f2fma(sh, pj[3], f2mul(ch, o[6]));
        // Tq = qmul(Tq, M)
        u64 tw = f2fma(nqx, Mx, f2fma(nqy, My, f2fma(nqz, Mz, f2mul(Tq.w, Mw))));
        u64 tx = f2fma(Tq.y, Mz, f2fma(nqz, My, f2fma(Tq.w, Mx, f2mul(Tq.x, Mw))));
        u64 ty = f2fma(Tq.z, Mx, f2fma(nqx, Mz, f2fma(Tq.w, My, f2mul(Tq.y, Mw))));
        u64 tz = f2fma(Tq.x, My, f2fma(nqy, Mx, f2fma(Tq.w, Mz, f2mul(Tq.z, Mw))));
        Tq.x = tx; Tq.y = ty; Tq.z = tz; Tq.w = tw;

        if ((j & 7) == 7) {   // TARGET_LINKS = 8,16,24,32
            int k = j >> 3;
            V2 rho, phi;
            pose_err2(U + U_TGT + k * 10, Tt, Tq, rho, phi);
            float a0, b0;
            f2unp(rho.x, a0, b0); row[k*6+0] = a0;        bres[k*6+0] = b0;
            f2unp(rho.y, a0, b0); row[k*6+1] = a0;        bres[k*6+1] = b0;
            f2unp(rho.z, a0, b0); row[k*6+2] = a0;        bres[k*6+2] = b0;
            f2unp(phi.x, a0, b0); row[k*6+3] = 0.5f*a0;   bres[k*6+3] = 0.5f*b0;
            f2unp(phi.y, a0, b0); row[k*6+4] = 0.5f*a0;   bres[k*6+4] = 0.5f*b0;
            f2unp(phi.z, a0, b0); row[k*6+5] = 0.5f*a0;   bres[k*6+5] = 0.5f*b0;
        }
    }

    // ---- base residuals ----
    {
        V2 rho, phi;
        pose_err2(U + U_DB, bt, bq, rho, phi);
        float a0, b0;
        f2unp(rho.x, a0, b0); row[88] = a0*5.0f; bres[24] = b0*5.0f;
        f2unp(rho.y, a0, b0); row[89] = a0*5.0f; bres[25] = b0*5.0f;
        f2unp(rho.z, a0, b0); row[90] = a0*5.0f; bres[26] = b0*5.0f;
        f2unp(phi.x, a0, b0); row[91] = a0*5.0f; bres[27] = b0*5.0f;
        f2unp(phi.y, a0, b0); row[92] = a0*5.0f; bres[28] = b0*5.0f;
        f2unp(phi.z, a0, b0); row[93] = a0*5.0f; bres[29] = b0*5.0f;
    }

    __syncthreads();

    // ---- flush phase 1: elements [e0, e0+128) ----
    {
        float4* go4 = (float4*)(out + (size_t)e0 * OUTC);
        const float4* s4 = (const float4*)s;
        for (int f = t; f < TPB * OUTC / 4; f += TPB) go4[f] = s4[f];
    }
    __syncthreads();

    // ---- phase 2: write B residuals ----
    #pragma unroll
    for (int i = 0; i < 24; i++) row[i] = bres[i];
    #pragma unroll
    for (int j = 0; j < NJ; j++) {
        float limB = fmaxf(thB[j] - UP[j], 0.0f) + fminf(thB[j] - LO[j], 0.0f);
        row[24 + j] = limB * 10.0f;
        row[56 + j] = (thB[j] - RST[j]) * 0.1f;
    }
    #pragma unroll
    for (int i = 0; i < 6; i++) row[88 + i] = bres[24 + i];

    __syncthreads();

    // ---- flush phase 2: elements [e0+128, e0+256) ----
    {
        float4* go4 = (float4*)(out + (size_t)(e0 + TPB) * OUTC);
        const float4* s4 = (const float4*)s;
        for (int f = t; f < TPB * OUTC / 4; f += TPB) go4[f] = s4[f];
    }
}

extern "C" void kernel_launch(void* const* d_in, const int* in_sizes, int n_in,
                              void* d_out, int out_size) {
    const float* cfg   = (const float*)d_in[0];
    const float* base  = (const float*)d_in[1];
    const float* tgt   = (const float*)d_in[2];
    const float* dbase = (const float*)d_in[3];
    const float* rest  = (const float*)d_in[4];
    const float* joff  = (const float*)d_in[5];
    const float* jaxis = (const float*)d_in[6];
    const float* jlo   = (const float*)d_in[7];
    const float* jup   = (const float*)d_in[8];
    float* out = (float*)d_out;

    cudaFuncSetAttribute(ik_residual_kernel,
                         cudaFuncAttributeMaxDynamicSharedMemorySize, SMEM_BYTES);

    int B = in_sizes[0] / NJ;     // 65536
    int nblocks = B / EPB;        // 256

    ik_residual_kernel<<<nblocks, TPB, SMEM_BYTES>>>(cfg, base, tgt, dbase, rest,
                                                     joff, jaxis, jlo, jup, out);
}

// round 5
// speedup vs baseline: 1.0846x; 1.0846x over previous
#include <cuda_runtime.h>

#define NJ   32
#define TPB  128
#define OUTC 94

// ---- dynamic smem float offsets (same plan as R2) ----
#define S_OUT   0
#define S_TGT   (TPB * OUTC)          // 12032  (4 x 7)
#define S_DB    (S_TGT + 28)          //        (7)
#define S_REST  (S_DB + 7)            //        (32)
#define S_JLO   (S_REST + 32)         //        (32)
#define S_JUP   (S_JLO + 32)          //        (32)
#define S_JOFF  (S_JUP + 32)          //        (32 x 7)
#define S_P     (S_JOFF + 224)        //        (32 x 4)
#define S_TOTAL (S_P + 128)           // 12515 floats = 50060 B

struct Q { float x, y, z, w; };
struct V { float x, y, z; };

__device__ __forceinline__ V vcross(V a, V b) {
    return {a.y * b.z - a.z * b.y,
            a.z * b.x - a.x * b.z,
            a.x * b.y - a.y * b.x};
}

// t + 2*(v x (v x t + w t))
__device__ __forceinline__ V qrot(Q q, V t) {
    V v{q.x, q.y, q.z};
    V u = vcross(v, t);
    u.x = fmaf(q.w, t.x, u.x);
    u.y = fmaf(q.w, t.y, u.y);
    u.z = fmaf(q.w, t.z, u.z);
    V c = vcross(v, u);
    return {fmaf(2.0f, c.x, t.x), fmaf(2.0f, c.y, t.y), fmaf(2.0f, c.z, t.z)};
}

__device__ __forceinline__ Q qmul(Q a, Q b) {
    Q r;
    r.w = a.w * b.w - a.x * b.x - a.y * b.y - a.z * b.z;
    r.x = a.w * b.x + b.w * a.x + a.y * b.z - a.z * b.y;
    r.y = a.w * b.y + b.w * a.y + a.z * b.x - a.x * b.z;
    r.z = a.w * b.z + b.w * a.z + a.x * b.y - a.y * b.x;
    return r;
}

// SE3 accumulate-left: (t1,q1) <- (t1,q1) o (t2,q2)
__device__ __forceinline__ void se3_acc(V& t1, Q& q1, V t2, Q q2) {
    V r = qrot(q1, t2);
    t1.x += r.x; t1.y += r.y; t1.z += r.z;
    q1 = qmul(q1, q2);
}

// atan2(y, x) for y >= 0, x >= 0, not both zero
__device__ __forceinline__ float atan2pos(float y, float x) {
    float mn = fminf(y, x), mx = fmaxf(y, x);
    float r  = __fdividef(mn, mx);
    float r2 = r * r;
    float p = fmaf(r2, -0.0117212f,  0.05265332f);
    p = fmaf(r2, p, -0.11643287f);
    p = fmaf(r2, p,  0.19354346f);
    p = fmaf(r2, p, -0.33262347f);
    p = fmaf(r2, p,  0.99997726f);
    float th = r * p;
    return (y > x) ? (1.57079632679489662f - th) : th;
}

// se3_log for UNIT quaternion (trig-free)
__device__ __forceinline__ void se3_log(V t, Q q, V& rho, V& phi) {
    float sgn = (q.w < 0.0f) ? -1.0f : 1.0f;
    float qx = q.x * sgn, qy = q.y * sgn, qz = q.z * sgn, qw = q.w * sgn;
    float nv2 = qx * qx + qy * qy + qz * qz;
    float nv  = sqrtf(fmaxf(nv2, 1e-14f));
    float angle = 2.0f * atan2pos(nv, qw);
    float wsafe = (fabsf(qw) > 1e-8f) ? qw : 1.0f;
    float scale = (nv < 1e-6f) ? __fdividef(2.0f, wsafe) : __fdividef(angle, nv);
    phi = {qx * scale, qy * scale, qz * scale};

    float th  = angle;
    float th2 = th * th;
    float abig = __fdividef(1.0f - 0.5f * scale * qw, th2);
    float a = (th < 1e-4f) ? (1.0f / 12.0f + th2 * (1.0f / 720.0f)) : abig;

    V pt  = vcross(phi, t);
    V ppt = vcross(phi, pt);
    rho = {t.x - 0.5f * pt.x + a * ppt.x,
           t.y - 0.5f * pt.y + a * ppt.y,
           t.z - 0.5f * pt.z + a * ppt.z};
}

// log( inv(target) o actual ), target pose (7 floats) from smem
__device__ __forceinline__ void pose_err_log(const float* tp, V at, Q aq,
                                             V& rho, V& phi) {
    Q qi{-tp[3], -tp[4], -tp[5], tp[6]};
    V d{at.x - tp[0], at.y - tp[1], at.z - tp[2]};
    V pe = qrot(qi, d);
    Q qe = qmul(qi, aq);
    se3_log(pe, qe, rho, phi);
}

__global__ void __launch_bounds__(TPB, 4)
ik_residual_kernel(const float* __restrict__ cfg,
                   const float* __restrict__ base,
                   const float* __restrict__ tgt,
                   const float* __restrict__ dbase,
                   const float* __restrict__ rest,
                   const float* __restrict__ joff,
                   const float* __restrict__ jaxis,
                   const float* __restrict__ jlo,
                   const float* __restrict__ jup,
                   float* __restrict__ out) {
    extern __shared__ float s[];

    const int t  = threadIdx.x;
    const int b0 = blockIdx.x * TPB;

    // ---- stage constants + base poses (scratch in S_OUT) ----
    {
        const float* gb = base + (size_t)b0 * 7;
        #pragma unroll
        for (int i = t; i < TPB * 7; i += TPB) s[S_OUT + i] = gb[i];
        #pragma unroll
        for (int i = t; i < 224; i += TPB) s[S_JOFF + i] = __ldg(joff + i);
        if (t < 28) s[S_TGT + t] = __ldg(tgt + t);
        if (t < 7)  s[S_DB + t]  = __ldg(dbase + t);
        if (t < 32) {
            s[S_REST + t] = __ldg(rest + t);
            s[S_JLO + t]  = __ldg(jlo + t);
            s[S_JUP + t]  = __ldg(jup + t);
            // P_j = oq_j (x) [axis_j, 0]
            float ox = __ldg(joff + t * 7 + 3), oy = __ldg(joff + t * 7 + 4);
            float oz = __ldg(joff + t * 7 + 5), ow = __ldg(joff + t * 7 + 6);
            float ax = __ldg(jaxis + t * 3 + 0), ay = __ldg(jaxis + t * 3 + 1);
            float az = __ldg(jaxis + t * 3 + 2);
            s[S_P + t * 4 + 0] = ow * ax + oy * az - oz * ay;
            s[S_P + t * 4 + 1] = ow * ay + oz * ax - ox * az;
            s[S_P + t * 4 + 2] = ow * az + ox * ay - oy * ax;
            s[S_P + t * 4 + 3] = -(ox * ax + oy * ay + oz * az);
        }
    }
    __syncthreads();

    float bp[7];
    #pragma unroll
    for (int i = 0; i < 7; i++) bp[i] = s[S_OUT + t * 7 + i];
    __syncthreads();   // scratch becomes output staging

    const int b = b0 + t;
    float* row = s + S_OUT + t * OUTC;

    V Tt{bp[0], bp[1], bp[2]};
    Q Tq{bp[3], bp[4], bp[5], bp[6]};

    const float4* c4 = (const float4*)(cfg + (size_t)b * NJ);

    // ---- tree-structured FK: 4 segments of 8 joints ----
    #pragma unroll
    for (int seg = 0; seg < 4; seg++) {
        const int j0 = seg * 8;
        float4 ca = __ldg(c4 + seg * 2);
        float4 cb = __ldg(c4 + seg * 2 + 1);
        float th[8] = {ca.x, ca.y, ca.z, ca.w, cb.x, cb.y, cb.z, cb.w};

        // leaf joint quats M_j = ch*oq_j + sh*P_j  (all independent)
        Q M[8];
        #pragma unroll
        for (int i = 0; i < 8; i++) {
            const int j = j0 + i;
            float lim = fmaxf(th[i] - s[S_JUP + j], 0.0f)
                      + fminf(th[i] - s[S_JLO + j], 0.0f);
            row[24 + j] = lim * 10.0f;
            row[56 + j] = (th[i] - s[S_REST + j]) * 0.1f;

            float sh, ch;
            __sincosf(0.5f * th[i], &sh, &ch);
            const float* o = s + S_JOFF + j * 7;
            const float* p = s + S_P + j * 4;
            M[i].x = fmaf(sh, p[0], ch * o[3]);
            M[i].y = fmaf(sh, p[1], ch * o[4]);
            M[i].z = fmaf(sh, p[2], ch * o[5]);
            M[i].w = fmaf(sh, p[3], ch * o[6]);
        }

        // leaf translations (warp-uniform smem loads)
        const float* o0 = s + S_JOFF + (j0 + 0) * 7;
        const float* o1 = s + S_JOFF + (j0 + 1) * 7;
        const float* o2 = s + S_JOFF + (j0 + 2) * 7;
        const float* o3 = s + S_JOFF + (j0 + 3) * 7;
        const float* o4 = s + S_JOFF + (j0 + 4) * 7;
        const float* o5 = s + S_JOFF + (j0 + 5) * 7;
        const float* o6 = s + S_JOFF + (j0 + 6) * 7;
        const float* o7 = s + S_JOFF + (j0 + 7) * 7;

        // level 1: 4 independent composes
        V t01{o0[0], o0[1], o0[2]}; Q q01 = M[0];
        se3_acc(t01, q01, V{o1[0], o1[1], o1[2]}, M[1]);
        V t23{o2[0], o2[1], o2[2]}; Q q23 = M[2];
        se3_acc(t23, q23, V{o3[0], o3[1], o3[2]}, M[3]);
        V t45{o4[0], o4[1], o4[2]}; Q q45 = M[4];
        se3_acc(t45, q45, V{o5[0], o5[1], o5[2]}, M[5]);
        V t67{o6[0], o6[1], o6[2]}; Q q67 = M[6];
        se3_acc(t67, q67, V{o7[0], o7[1], o7[2]}, M[7]);

        // level 2: 2 independent composes
        se3_acc(t01, q01, t23, q23);
        se3_acc(t45, q45, t67, q67);

        // level 3: segment product
        se3_acc(t01, q01, t45, q45);

        // chain into running pose (prefix product at target link)
        se3_acc(Tt, Tq, t01, q01);

        // pose residual at this target link
        V rho, phi;
        pose_err_log(s + S_TGT + seg * 7, Tt, Tq, rho, phi);
        row[seg * 6 + 0] = rho.x;
        row[seg * 6 + 1] = rho.y;
        row[seg * 6 + 2] = rho.z;
        row[seg * 6 + 3] = 0.5f * phi.x;
        row[seg * 6 + 4] = 0.5f * phi.y;
        row[seg * 6 + 5] = 0.5f * phi.z;
    }

    // ---- base residual ----
    {
        V rho, phi;
        pose_err_log(s + S_DB, V{bp[0], bp[1], bp[2]},
                     Q{bp[3], bp[4], bp[5], bp[6]}, rho, phi);
        row[88] = rho.x * 5.0f;
        row[89] = rho.y * 5.0f;
        row[90] = rho.z * 5.0f;
        row[91] = phi.x * 5.0f;
        row[92] = phi.y * 5.0f;
        row[93] = phi.z * 5.0f;
    }

    __syncthreads();

    // ---- flat vectorized flush ----
    {
        float4* go4 = (float4*)(out + (size_t)b0 * OUTC);
        const float4* s4 = (const float4*)(s + S_OUT);
        for (int f = t; f < TPB * OUTC / 4; f += TPB) go4[f] = s4[f];
    }
}

extern "C" void kernel_launch(void* const* d_in, const int* in_sizes, int n_in,
                              void* d_out, int out_size) {
    const float* cfg   = (const float*)d_in[0];
    const float* base  = (const float*)d_in[1];
    const float* tgt   = (const float*)d_in[2];
    const float* dbase = (const float*)d_in[3];
    const float* rest  = (const float*)d_in[4];
    const float* joff  = (const float*)d_in[5];
    const float* jaxis = (const float*)d_in[6];
    const float* jlo   = (const float*)d_in[7];
    const float* jup   = (const float*)d_in[8];
    float* out = (float*)d_out;

    const int smem_bytes = S_TOTAL * sizeof(float);   // 50060
    cudaFuncSetAttribute(ik_residual_kernel,
                         cudaFuncAttributeMaxDynamicSharedMemorySize, smem_bytes);

    int B = in_sizes[0] / NJ;     // 65536
    int nblocks = B / TPB;        // 512

    ik_residual_kernel<<<nblocks, TPB, smem_bytes>>>(cfg, base, tgt, dbase, rest,
                                                     joff, jaxis, jlo, jup, out);
}